// round 15
// baseline (speedup 1.0000x reference)
#include <cuda_runtime.h>
#include <cuda_bf16.h>
#include <math.h>

#define BINS 10
#define BLOCK 256
#define GRID  1184   // 148 SMs * 8 (grid-stride; also fine on 152-SM parts)

// Global scratch (no allocations allowed).
// Zero at module load; ghm_final re-zeroes after each use -> every launch
// (first call, capture, and every graph replay) starts from zeroed state.
__device__ double       g_sum[BINS];
__device__ unsigned int g_cnt[BINS];

__device__ __forceinline__ void process_elem(float p, float t, float w,
                                             float* s_sum, float* s_cnt, int tid) {
    if (w > 0.0f) {
        float ap = fabsf(p);
        float e  = __expf(-ap);          // exp(-|p|), shared by sigmoid and log1p term
        float r  = __frcp_rn(1.0f + e);  // 1/(1+e)
        float s  = (p >= 0.0f) ? r : e * r;   // sigmoid(p)
        float g  = fabsf(s - t);
        int bin  = (int)(g * 10.0f);
        bin = bin > (BINS - 1) ? (BINS - 1) : bin;
        // bce = max(p,0) - p*t + log1p(exp(-|p|)); log(1+e) is accurate enough (e<=1)
        float bce = fmaxf(p, 0.0f) - p * t + __logf(1.0f + e);
        s_sum[bin * BLOCK + tid] += bce;
        s_cnt[bin * BLOCK + tid] += 1.0f;
    }
}

__global__ void __launch_bounds__(BLOCK)
ghm_main(const float* __restrict__ pred,
         const float* __restrict__ target,
         const float* __restrict__ lw,
         int n) {
    // Per-thread private histogram columns: [bin][tid] -> bank = tid%32, conflict-free.
    __shared__ float s_sum[BINS * BLOCK];
    __shared__ float s_cnt[BINS * BLOCK];

    const int tid = threadIdx.x;
#pragma unroll
    for (int b = 0; b < BINS; b++) {
        s_sum[b * BLOCK + tid] = 0.0f;
        s_cnt[b * BLOCK + tid] = 0.0f;
    }

    const int n4 = n >> 2;
    const float4* __restrict__ p4 = (const float4*)pred;
    const float4* __restrict__ t4 = (const float4*)target;
    const float4* __restrict__ w4 = (const float4*)lw;

    const int stride = gridDim.x * BLOCK;
    for (int i = blockIdx.x * BLOCK + tid; i < n4; i += stride) {
        float4 p = p4[i];
        float4 t = t4[i];
        float4 w = w4[i];
        process_elem(p.x, t.x, w.x, s_sum, s_cnt, tid);
        process_elem(p.y, t.y, w.y, s_sum, s_cnt, tid);
        process_elem(p.z, t.z, w.z, s_sum, s_cnt, tid);
        process_elem(p.w, t.w, w.w, s_sum, s_cnt, tid);
    }
    // Scalar tail (n not multiple of 4) — block 0 only.
    if (blockIdx.x == 0) {
        for (int i = (n4 << 2) + tid; i < n; i += BLOCK)
            process_elem(pred[i], target[i], lw[i], s_sum, s_cnt, tid);
    }

    __syncthreads();
    // Tree-reduce each bin's 256 partials.
    for (int s = BLOCK / 2; s > 0; s >>= 1) {
        if (tid < s) {
#pragma unroll
            for (int b = 0; b < BINS; b++) {
                s_sum[b * BLOCK + tid] += s_sum[b * BLOCK + tid + s];
                s_cnt[b * BLOCK + tid] += s_cnt[b * BLOCK + tid + s];
            }
        }
        __syncthreads();
    }
    if (tid < BINS) {
        atomicAdd(&g_sum[tid], (double)s_sum[tid * BLOCK]);
        atomicAdd(&g_cnt[tid], (unsigned int)s_cnt[tid * BLOCK]);
    }

    // PDL: release the dependent grid once all CTAs reach here (atomics issued),
    // instead of waiting for full CTA teardown/drain.
    cudaTriggerProgrammaticLaunchCompletion();
}

__global__ void ghm_final(float* __restrict__ out) {
    // PDL: launched while ghm_main drains; block until ghm_main's CTAs have all
    // triggered and their memory (the atomics) is visible.
    cudaGridDependencySynchronize();

    const int b = threadIdx.x;   // one warp; lanes 0..9 own one bin each
    double term = 0.0;
    int    ne   = 0;
    if (b < BINS) {
        unsigned int c = g_cnt[b];   // 10 loads in flight concurrently
        double       s = g_sum[b];
        if (c > 0u) { term = s / (double)c; ne = 1; }  // parallel DDIVs
        // Self-clean for the next launch/replay.
        g_sum[b] = 0.0;
        g_cnt[b] = 0u;
    }
#pragma unroll
    for (int o = 16; o > 0; o >>= 1) {
        term += __shfl_down_sync(0xFFFFFFFFu, term, o);
        ne   += __shfl_down_sync(0xFFFFFFFFu, ne, o);
    }
    if (b == 0) {
        float loss = (ne > 0) ? (float)(term / (double)ne) : 0.0f;
        out[0] = loss * 1.0f;   // LOSS_WEIGHT
    }
}

extern "C" void kernel_launch(void* const* d_in, const int* in_sizes, int n_in,
                              void* d_out, int out_size) {
    const float* pred   = (const float*)d_in[0];
    const float* target = (const float*)d_in[1];
    const float* lw     = (const float*)d_in[2];
    float* out = (float*)d_out;
    int n = in_sizes[0];

    ghm_main<<<GRID, BLOCK>>>(pred, target, lw, n);

    // Launch ghm_final with programmatic stream serialization (PDL): its setup
    // overlaps ghm_main's drain; cudaGridDependencySynchronize() inside provides
    // the actual dependency.
    cudaLaunchConfig_t cfg = {};
    cfg.gridDim  = dim3(1, 1, 1);
    cfg.blockDim = dim3(32, 1, 1);
    cfg.dynamicSmemBytes = 0;
    cfg.stream = 0;   // same (capturing) stream as the <<<>>> launch above
    cudaLaunchAttribute attr[1];
    attr[0].id = cudaLaunchAttributeProgrammaticStreamSerialization;
    attr[0].val.programmaticStreamSerializationAllowed = 1;
    cfg.attrs = attr;
    cfg.numAttrs = 1;
    cudaLaunchKernelEx(&cfg, ghm_final, out);
}

// round 16
// speedup vs baseline: 1.0132x; 1.0132x over previous
#include <cuda_runtime.h>
#include <cuda_bf16.h>
#include <math.h>

#define BINS 10
#define BLOCK 256
#define GRID  1184   // 148 SMs * 8 (grid-stride; also fine on 152-SM parts)

// Global scratch (no allocations allowed).
// Zero at module load; ghm_final re-zeroes after each use -> every launch
// (first call, capture, and every graph replay) starts from zeroed state.
__device__ double       g_sum[BINS];
__device__ unsigned int g_cnt[BINS];

__device__ __forceinline__ void process_elem(float p, float t, float w,
                                             float* s_sum, float* s_cnt, int tid) {
    if (w > 0.0f) {
        float ap = fabsf(p);
        float e  = __expf(-ap);          // exp(-|p|), shared by sigmoid and log1p term
        float r  = __frcp_rn(1.0f + e);  // 1/(1+e)
        float s  = (p >= 0.0f) ? r : e * r;   // sigmoid(p)
        float g  = fabsf(s - t);
        int bin  = (int)(g * 10.0f);
        bin = bin > (BINS - 1) ? (BINS - 1) : bin;
        // bce = max(p,0) - p*t + log1p(exp(-|p|)); log(1+e) is accurate enough (e<=1)
        float bce = fmaxf(p, 0.0f) - p * t + __logf(1.0f + e);
        s_sum[bin * BLOCK + tid] += bce;
        s_cnt[bin * BLOCK + tid] += 1.0f;
    }
}

__global__ void __launch_bounds__(BLOCK)
ghm_main(const float* __restrict__ pred,
         const float* __restrict__ target,
         const float* __restrict__ lw,
         int n) {
    // Per-thread private histogram columns: [bin][tid] -> bank = tid%32, conflict-free.
    __shared__ float s_sum[BINS * BLOCK];
    __shared__ float s_cnt[BINS * BLOCK];

    const int tid = threadIdx.x;
#pragma unroll
    for (int b = 0; b < BINS; b++) {
        s_sum[b * BLOCK + tid] = 0.0f;
        s_cnt[b * BLOCK + tid] = 0.0f;
    }

    const int n4 = n >> 2;
    const float4* __restrict__ p4 = (const float4*)pred;
    const float4* __restrict__ t4 = (const float4*)target;
    const float4* __restrict__ w4 = (const float4*)lw;

    const int stride = gridDim.x * BLOCK;
    for (int i = blockIdx.x * BLOCK + tid; i < n4; i += stride) {
        float4 p = p4[i];
        float4 t = t4[i];
        float4 w = w4[i];
        process_elem(p.x, t.x, w.x, s_sum, s_cnt, tid);
        process_elem(p.y, t.y, w.y, s_sum, s_cnt, tid);
        process_elem(p.z, t.z, w.z, s_sum, s_cnt, tid);
        process_elem(p.w, t.w, w.w, s_sum, s_cnt, tid);
    }
    // Scalar tail (n not multiple of 4) — block 0 only.
    if (blockIdx.x == 0) {
        for (int i = (n4 << 2) + tid; i < n; i += BLOCK)
            process_elem(pred[i], target[i], lw[i], s_sum, s_cnt, tid);
    }

    __syncthreads();
    // Tree-reduce each bin's 256 partials.
    for (int s = BLOCK / 2; s > 0; s >>= 1) {
        if (tid < s) {
#pragma unroll
            for (int b = 0; b < BINS; b++) {
                s_sum[b * BLOCK + tid] += s_sum[b * BLOCK + tid + s];
                s_cnt[b * BLOCK + tid] += s_cnt[b * BLOCK + tid + s];
            }
        }
        __syncthreads();
    }
    if (tid < BINS) {
        atomicAdd(&g_sum[tid], (double)s_sum[tid * BLOCK]);
        atomicAdd(&g_cnt[tid], (unsigned int)s_cnt[tid * BLOCK]);
    }
}

__global__ void ghm_final(float* __restrict__ out) {
    // PDL: this grid launches while ghm_main drains; block here until ghm_main
    // (and its atomics) are complete/visible, hiding the launch latency.
    cudaGridDependencySynchronize();

    const int b = threadIdx.x;   // one warp; lanes 0..9 own one bin each
    double term = 0.0;
    int    ne   = 0;
    if (b < BINS) {
        unsigned int c = g_cnt[b];   // 10 loads in flight concurrently
        double       s = g_sum[b];
        if (c > 0u) { term = s / (double)c; ne = 1; }  // parallel DDIVs
        // Self-clean for the next launch/replay.
        g_sum[b] = 0.0;
        g_cnt[b] = 0u;
    }
#pragma unroll
    for (int o = 16; o > 0; o >>= 1) {
        term += __shfl_down_sync(0xFFFFFFFFu, term, o);
        ne   += __shfl_down_sync(0xFFFFFFFFu, ne, o);
    }
    if (b == 0) {
        float loss = (ne > 0) ? (float)(term / (double)ne) : 0.0f;
        out[0] = loss * 1.0f;   // LOSS_WEIGHT
    }
}

extern "C" void kernel_launch(void* const* d_in, const int* in_sizes, int n_in,
                              void* d_out, int out_size) {
    const float* pred   = (const float*)d_in[0];
    const float* target = (const float*)d_in[1];
    const float* lw     = (const float*)d_in[2];
    float* out = (float*)d_out;
    int n = in_sizes[0];

    ghm_main<<<GRID, BLOCK>>>(pred, target, lw, n);

    // Launch ghm_final with programmatic stream serialization (PDL): its setup
    // overlaps ghm_main's drain; cudaGridDependencySynchronize() inside provides
    // the actual dependency.
    cudaLaunchConfig_t cfg = {};
    cfg.gridDim  = dim3(1, 1, 1);
    cfg.blockDim = dim3(32, 1, 1);
    cfg.dynamicSmemBytes = 0;
    cfg.stream = 0;   // same (capturing) stream as the <<<>>> launch above
    cudaLaunchAttribute attr[1];
    attr[0].id = cudaLaunchAttributeProgrammaticStreamSerialization;
    attr[0].val.programmaticStreamSerializationAllowed = 1;
    cfg.attrs = attr;
    cfg.numAttrs = 1;
    cudaLaunchKernelEx(&cfg, ghm_final, out);
}